// round 3
// baseline (speedup 1.0000x reference)
#include <cuda_runtime.h>
#include <cuda_bf16.h>

#define NU 100000
#define NI 100000
#define EE 1600000
#define C  128
#define C2 (C / 2)          // bfloat162 per row
#define LN_EPS 1e-5f

#define SCAN_T     256
#define SCAN_E     4
#define SCAN_CHUNK (SCAN_T * SCAN_E)   // 1024
#define NB_U ((NU + SCAN_CHUNK - 1) / SCAN_CHUNK)
#define NB_I ((NI + SCAN_CHUNK - 1) / SCAN_CHUNK)

// ---- scratch (allocation-free rule: device globals) ----
__device__ int   g_deg_u[NU];
__device__ int   g_deg_i[NI];
__device__ int   g_off_u[NU + 1];
__device__ int   g_off_i[NI + 1];
__device__ int   g_cur_u[NU];
__device__ int   g_cur_i[NI];
__device__ int   g_bsum_u[NB_U];
__device__ int   g_bsum_i[NB_I];
__device__ int2  g_csr_iu[EE];            // edges into user nodes: {src_item, w}
__device__ int2  g_csr_ui[EE];            // edges into item nodes: {src_user, w}
__device__ float g_u1[(size_t)NU * C];    // layer-0 output fp32 (root for layer 1)
__device__ float g_i1[(size_t)NI * C];
__device__ __nv_bfloat162 g_xub[(size_t)NU * C2];  // bf16 gather tables
__device__ __nv_bfloat162 g_xib[(size_t)NI * C2];
__device__ __nv_bfloat162 g_u1b[(size_t)NU * C2];
__device__ __nv_bfloat162 g_i1b[(size_t)NI * C2];

// ---------------------------------------------------------------------------
// fp32 -> bf16 table conversion (one bfloat162 per thread)
// ---------------------------------------------------------------------------
__global__ void cvt_bf16_kernel(const float2* __restrict__ in,
                                __nv_bfloat162* __restrict__ out, int n2) {
    int i = blockIdx.x * blockDim.x + threadIdx.x;
    if (i < n2) {
        float2 v = __ldg(in + i);
        out[i] = __floats2bfloat162_rn(v.x, v.y);
    }
}

// ---------------------------------------------------------------------------
// in-degree histogram
// ---------------------------------------------------------------------------
__global__ void count_kernel(const int* __restrict__ ei_dst,
                             int* __restrict__ deg, int E) {
    int e = blockIdx.x * blockDim.x + threadIdx.x;
    if (e < E) atomicAdd(&deg[ei_dst[e]], 1);
}

// ---------------------------------------------------------------------------
// exclusive prefix scan (3 kernels)
// ---------------------------------------------------------------------------
__global__ void scan1_kernel(const int* __restrict__ in, int* __restrict__ out,
                             int* __restrict__ bsum, int N) {
    __shared__ int sh[SCAN_T];
    int base = blockIdx.x * SCAN_CHUNK + threadIdx.x * SCAN_E;
    int v[SCAN_E];
    int s = 0;
#pragma unroll
    for (int i = 0; i < SCAN_E; i++) {
        int idx = base + i;
        v[i] = (idx < N) ? in[idx] : 0;
        s += v[i];
    }
    sh[threadIdx.x] = s;
    __syncthreads();
    for (int o = 1; o < SCAN_T; o <<= 1) {
        int val = sh[threadIdx.x];
        int add = (threadIdx.x >= o) ? sh[threadIdx.x - o] : 0;
        __syncthreads();
        sh[threadIdx.x] = val + add;
        __syncthreads();
    }
    int run = sh[threadIdx.x] - s;
#pragma unroll
    for (int i = 0; i < SCAN_E; i++) {
        int idx = base + i;
        if (idx < N) out[idx] = run;
        run += v[i];
    }
    if (threadIdx.x == SCAN_T - 1) bsum[blockIdx.x] = sh[SCAN_T - 1];
}

__global__ void scan2_kernel(int* __restrict__ bsum, int nb) {
    __shared__ int sh[256];
    int t = threadIdx.x;
    sh[t] = (t < nb) ? bsum[t] : 0;
    __syncthreads();
    if (t == 0) {
        int run = 0;
        for (int i = 0; i < nb; i++) { int x = sh[i]; sh[i] = run; run += x; }
    }
    __syncthreads();
    if (t < nb) bsum[t] = sh[t];
}

__global__ void scan3_kernel(int* __restrict__ out, const int* __restrict__ bsum,
                             int N, int total) {
    int i = blockIdx.x * blockDim.x + threadIdx.x;
    if (i < N) out[i] += bsum[i / SCAN_CHUNK];
    if (i == 0) out[N] = total;
}

// ---------------------------------------------------------------------------
// CSR fill: group edges by destination
// ---------------------------------------------------------------------------
__global__ void fill_csr_kernel(const int* __restrict__ ei,
                                const float* __restrict__ ew,
                                int* __restrict__ cursor,
                                int2* __restrict__ csr, int E) {
    int e = blockIdx.x * blockDim.x + threadIdx.x;
    if (e >= E) return;
    int   src = ei[e];
    int   dst = ei[E + e];
    float w   = ew[e];
    int pos = atomicAdd(&cursor[dst], 1);
    csr[pos] = make_int2(src, __float_as_int(w));
}

// ---------------------------------------------------------------------------
// fused gather(bf16 src) + mean + root(fp32) + LayerNorm (+ReLU).
// One warp per dst node; lane covers channels [4*lane, 4*lane+3].
// Optionally also emits a bf16 copy (gather source for the next layer).
// ---------------------------------------------------------------------------
__device__ __forceinline__ void accum_row(float4& acc, const uint2 r, float w) {
    __nv_bfloat162 a = *reinterpret_cast<const __nv_bfloat162*>(&r.x);
    __nv_bfloat162 b = *reinterpret_cast<const __nv_bfloat162*>(&r.y);
    float2 f0 = __bfloat1622float2(a);
    float2 f1 = __bfloat1622float2(b);
    acc.x = fmaf(w, f0.x, acc.x);
    acc.y = fmaf(w, f0.y, acc.y);
    acc.z = fmaf(w, f1.x, acc.z);
    acc.w = fmaf(w, f1.y, acc.w);
}

__global__ void gather_combine_kernel(const int* __restrict__ off,
                                      const int2* __restrict__ csr,
                                      const uint2* __restrict__ xsrc,   // bf16 rows, 32 uint2/row
                                      const float* __restrict__ xdst,   // fp32 rows
                                      const float* __restrict__ lnw,
                                      const float* __restrict__ lnb,
                                      float* __restrict__ out_f,
                                      uint2* __restrict__ out_b,        // may be null
                                      int N, int do_relu) {
    int gw   = (blockIdx.x * blockDim.x + threadIdx.x) >> 5;
    int lane = threadIdx.x & 31;
    if (gw >= N) return;

    int beg = __ldg(off + gw);
    int end = __ldg(off + gw + 1);

    float4 acc = make_float4(0.f, 0.f, 0.f, 0.f);
    int e = beg;
    for (; e + 3 < end; e += 4) {
        int2 p0 = __ldg(csr + e);
        int2 p1 = __ldg(csr + e + 1);
        int2 p2 = __ldg(csr + e + 2);
        int2 p3 = __ldg(csr + e + 3);
        uint2 r0 = __ldg(xsrc + (size_t)p0.x * 32 + lane);
        uint2 r1 = __ldg(xsrc + (size_t)p1.x * 32 + lane);
        uint2 r2 = __ldg(xsrc + (size_t)p2.x * 32 + lane);
        uint2 r3 = __ldg(xsrc + (size_t)p3.x * 32 + lane);
        accum_row(acc, r0, __int_as_float(p0.y));
        accum_row(acc, r1, __int_as_float(p1.y));
        accum_row(acc, r2, __int_as_float(p2.y));
        accum_row(acc, r3, __int_as_float(p3.y));
    }
    for (; e < end; e++) {
        int2 p0 = __ldg(csr + e);
        uint2 r0 = __ldg(xsrc + (size_t)p0.x * 32 + lane);
        accum_row(acc, r0, __int_as_float(p0.y));
    }

    float rc = 1.0f / fmaxf((float)(end - beg), 1.0f);

    float4 x = __ldg(reinterpret_cast<const float4*>(xdst + (size_t)gw * C) + lane);
    float4 v;
    v.x = fmaf(acc.x, rc, x.x);
    v.y = fmaf(acc.y, rc, x.y);
    v.z = fmaf(acc.z, rc, x.z);
    v.w = fmaf(acc.w, rc, x.w);

    float m = v.x + v.y + v.z + v.w;
#pragma unroll
    for (int o = 16; o > 0; o >>= 1) m += __shfl_xor_sync(0xffffffffu, m, o);
    m *= (1.0f / C);

    float4 d;
    d.x = v.x - m; d.y = v.y - m; d.z = v.z - m; d.w = v.w - m;

    float var = d.x * d.x + d.y * d.y + d.z * d.z + d.w * d.w;
#pragma unroll
    for (int o = 16; o > 0; o >>= 1) var += __shfl_xor_sync(0xffffffffu, var, o);
    var *= (1.0f / C);

    float inv = rsqrtf(var + LN_EPS);

    float4 wv = __ldg(reinterpret_cast<const float4*>(lnw) + lane);
    float4 bv = __ldg(reinterpret_cast<const float4*>(lnb) + lane);

    float4 o4;
    o4.x = fmaf(d.x * inv, wv.x, bv.x);
    o4.y = fmaf(d.y * inv, wv.y, bv.y);
    o4.z = fmaf(d.z * inv, wv.z, bv.z);
    o4.w = fmaf(d.w * inv, wv.w, bv.w);

    if (do_relu) {
        o4.x = fmaxf(o4.x, 0.0f);
        o4.y = fmaxf(o4.y, 0.0f);
        o4.z = fmaxf(o4.z, 0.0f);
        o4.w = fmaxf(o4.w, 0.0f);
    }

    *(reinterpret_cast<float4*>(out_f + (size_t)gw * C) + lane) = o4;

    if (out_b) {
        uint2 pk;
        __nv_bfloat162 lo = __floats2bfloat162_rn(o4.x, o4.y);
        __nv_bfloat162 hi = __floats2bfloat162_rn(o4.z, o4.w);
        pk.x = *reinterpret_cast<const unsigned int*>(&lo);
        pk.y = *reinterpret_cast<const unsigned int*>(&hi);
        out_b[(size_t)gw * 32 + lane] = pk;
    }
}

extern "C" void kernel_launch(void* const* d_in, const int* in_sizes, int n_in,
                              void* d_out, int out_size) {
    const float* x_user = (const float*)d_in[0];
    const float* x_item = (const float*)d_in[1];
    const float* ew_ui  = (const float*)d_in[2];
    const float* ew_iu  = (const float*)d_in[3];
    const float* lnwu0  = (const float*)d_in[4];
    const float* lnbu0  = (const float*)d_in[5];
    const float* lnwu1  = (const float*)d_in[6];
    const float* lnbu1  = (const float*)d_in[7];
    const float* lnwi0  = (const float*)d_in[8];
    const float* lnbi0  = (const float*)d_in[9];
    const float* lnwi1  = (const float*)d_in[10];
    const float* lnbi1  = (const float*)d_in[11];
    const int*   ei_ui  = (const int*)d_in[12];
    const int*   ei_iu  = (const int*)d_in[13];
    float*       out    = (float*)d_out;

    int *deg_u, *deg_i, *off_u, *off_i, *cur_u, *cur_i, *bsum_u, *bsum_i;
    int2 *csr_iu, *csr_ui;
    float *u1, *i1;
    __nv_bfloat162 *xub, *xib, *u1b, *i1b;
    cudaGetSymbolAddress((void**)&deg_u, g_deg_u);
    cudaGetSymbolAddress((void**)&deg_i, g_deg_i);
    cudaGetSymbolAddress((void**)&off_u, g_off_u);
    cudaGetSymbolAddress((void**)&off_i, g_off_i);
    cudaGetSymbolAddress((void**)&cur_u, g_cur_u);
    cudaGetSymbolAddress((void**)&cur_i, g_cur_i);
    cudaGetSymbolAddress((void**)&bsum_u, g_bsum_u);
    cudaGetSymbolAddress((void**)&bsum_i, g_bsum_i);
    cudaGetSymbolAddress((void**)&csr_iu, g_csr_iu);
    cudaGetSymbolAddress((void**)&csr_ui, g_csr_ui);
    cudaGetSymbolAddress((void**)&u1, g_u1);
    cudaGetSymbolAddress((void**)&i1, g_i1);
    cudaGetSymbolAddress((void**)&xub, g_xub);
    cudaGetSymbolAddress((void**)&xib, g_xib);
    cudaGetSymbolAddress((void**)&u1b, g_u1b);
    cudaGetSymbolAddress((void**)&i1b, g_i1b);

    const int EB   = 256;
    const int EG   = (EE + EB - 1) / EB;
    const int GC_U = NU / 8;     // warp per node, 8 warps/block
    const int GC_I = NI / 8;
    const int NCV  = NU * C2;    // bfloat162 elements per table

    // ---- bf16 tables for layer-0 gather sources ----
    cvt_bf16_kernel<<<(NCV + 255) / 256, 256>>>((const float2*)x_user, xub, NCV);
    cvt_bf16_kernel<<<(NCV + 255) / 256, 256>>>((const float2*)x_item, xib, NCV);

    // ---- CSR build (layer-invariant; reused by both layers) ----
    cudaMemsetAsync(deg_u, 0, NU * sizeof(int));
    cudaMemsetAsync(deg_i, 0, NI * sizeof(int));
    count_kernel<<<EG, EB>>>(ei_iu + EE, deg_u, EE);
    count_kernel<<<EG, EB>>>(ei_ui + EE, deg_i, EE);

    scan1_kernel<<<NB_U, SCAN_T>>>(deg_u, off_u, bsum_u, NU);
    scan2_kernel<<<1, 256>>>(bsum_u, NB_U);
    scan3_kernel<<<(NU + 255) / 256, 256>>>(off_u, bsum_u, NU, EE);

    scan1_kernel<<<NB_I, SCAN_T>>>(deg_i, off_i, bsum_i, NI);
    scan2_kernel<<<1, 256>>>(bsum_i, NB_I);
    scan3_kernel<<<(NI + 255) / 256, 256>>>(off_i, bsum_i, NI, EE);

    cudaMemcpyAsync(cur_u, off_u, NU * sizeof(int), cudaMemcpyDeviceToDevice);
    cudaMemcpyAsync(cur_i, off_i, NI * sizeof(int), cudaMemcpyDeviceToDevice);
    fill_csr_kernel<<<EG, EB>>>(ei_iu, ew_iu, cur_u, csr_iu, EE);
    fill_csr_kernel<<<EG, EB>>>(ei_ui, ew_ui, cur_i, csr_ui, EE);

    // ---- layer 0 (emit fp32 root + bf16 gather table for layer 1) ----
    gather_combine_kernel<<<GC_U, 256>>>(off_u, csr_iu, (const uint2*)xib, x_user,
                                         lnwu0, lnbu0, u1, (uint2*)u1b, NU, 1);
    gather_combine_kernel<<<GC_I, 256>>>(off_i, csr_ui, (const uint2*)xub, x_item,
                                         lnwi0, lnbi0, i1, (uint2*)i1b, NI, 1);

    // ---- layer 1 (final outputs, fp32 only) ----
    gather_combine_kernel<<<GC_U, 256>>>(off_u, csr_iu, (const uint2*)i1b, u1,
                                         lnwu1, lnbu1, out, (uint2*)nullptr, NU, 0);
    gather_combine_kernel<<<GC_I, 256>>>(off_i, csr_ui, (const uint2*)u1b, i1,
                                         lnwi1, lnbi1, out + (size_t)NU * C,
                                         (uint2*)nullptr, NI, 0);
}